// round 1
// baseline (speedup 1.0000x reference)
#include <cuda_runtime.h>
#include <cuda_bf16.h>
#include <cstdint>

#define N_NODES 50000
#define N_EDGES 500000
#define HID 128

// ---------------- scratch (device globals; no allocations allowed) ------------
__device__ int   g_deg[N_NODES];
__device__ int   g_off[N_NODES + 1];
__device__ int   g_cursor[N_NODES];
__device__ int   g_srcs[N_EDGES];
__device__ float g_agg[(size_t)N_NODES * HID];
__device__ float g_h1 [(size_t)N_NODES * HID];
__device__ float g_h2 [(size_t)N_NODES * HID];

// ---------------- CSR build ---------------------------------------------------
__global__ void zero_deg_kernel(int* deg, int n) {
    int i = blockIdx.x * blockDim.x + threadIdx.x;
    if (i < n) deg[i] = 0;
}

__global__ void count_deg_kernel(const int* __restrict__ dst, int* __restrict__ deg, int E) {
    int e = blockIdx.x * blockDim.x + threadIdx.x;
    if (e < E) atomicAdd(&deg[dst[e]], 1);
}

// single-block scan, 1024 threads, 4 elems/thread/iter
__global__ void scan_kernel(const int* __restrict__ deg, int* __restrict__ off, int N) {
    __shared__ int warp_sums[32];
    __shared__ int s_carry;
    int tid = threadIdx.x, lane = tid & 31, wid = tid >> 5;
    if (tid == 0) s_carry = 0;
    __syncthreads();
    for (int base = 0; base < N; base += 4096) {
        int idx = base + tid * 4;
        int v0 = (idx + 0 < N) ? deg[idx + 0] : 0;
        int v1 = (idx + 1 < N) ? deg[idx + 1] : 0;
        int v2 = (idx + 2 < N) ? deg[idx + 2] : 0;
        int v3 = (idx + 3 < N) ? deg[idx + 3] : 0;
        int s1 = v0, s2 = s1 + v1, s3 = s2 + v2, s4 = s3 + v3;
        // warp inclusive scan of per-thread totals
        int x = s4;
        #pragma unroll
        for (int o = 1; o < 32; o <<= 1) {
            int t = __shfl_up_sync(0xFFFFFFFFu, x, o);
            if (lane >= o) x += t;
        }
        if (lane == 31) warp_sums[wid] = x;
        __syncthreads();
        if (wid == 0) {
            int y = warp_sums[lane];
            #pragma unroll
            for (int o = 1; o < 32; o <<= 1) {
                int t = __shfl_up_sync(0xFFFFFFFFu, y, o);
                if (lane >= o) y += t;
            }
            warp_sums[lane] = y;
        }
        __syncthreads();
        int warp_off = (wid > 0) ? warp_sums[wid - 1] : 0;
        int excl = (x - s4) + warp_off + s_carry;  // exclusive prefix for this thread
        if (idx + 0 < N) off[idx + 0] = excl;
        if (idx + 1 < N) off[idx + 1] = excl + s1;
        if (idx + 2 < N) off[idx + 2] = excl + s2;
        if (idx + 3 < N) off[idx + 3] = excl + s3;
        __syncthreads();
        if (tid == 0) s_carry += warp_sums[31];
        __syncthreads();
    }
    if (threadIdx.x == 0) off[N] = s_carry;
}

__global__ void copy_cursor_kernel(const int* __restrict__ off, int* __restrict__ cur, int N) {
    int i = blockIdx.x * blockDim.x + threadIdx.x;
    if (i < N) cur[i] = off[i];
}

__global__ void fill_csr_kernel(const int* __restrict__ src, const int* __restrict__ dst,
                                int* __restrict__ cur, int* __restrict__ srcs, int E) {
    int e = blockIdx.x * blockDim.x + threadIdx.x;
    if (e < E) {
        int d = dst[e];
        int pos = atomicAdd(&cur[d], 1);
        srcs[pos] = src[e];
    }
}

// ---------------- mean aggregation: one warp per node -------------------------
__global__ void agg_kernel(const float* __restrict__ x, float* __restrict__ agg,
                           const int* __restrict__ off, const int* __restrict__ srcs, int N) {
    int warp = (blockIdx.x * blockDim.x + threadIdx.x) >> 5;
    int lane = threadIdx.x & 31;
    if (warp >= N) return;
    int s = off[warp], e = off[warp + 1];
    float4 acc = make_float4(0.f, 0.f, 0.f, 0.f);
    for (int j = s; j < e; ++j) {
        int u = srcs[j];  // uniform across warp
        float4 v = ((const float4*)(x + (size_t)u * HID))[lane];
        acc.x += v.x; acc.y += v.y; acc.z += v.z; acc.w += v.w;
    }
    float inv = 1.0f / (float)max(e - s, 1);
    acc.x *= inv; acc.y *= inv; acc.z *= inv; acc.w *= inv;
    ((float4*)(agg + (size_t)warp * HID))[lane] = acc;
}

// ---------------- fused SGEMM: out = relu?(agg@Wl + x@Wr + b) ----------------
// Tile: 64 nodes x OUTC cols per CTA. Full W (256 x OUTC) in smem; A transposed
// in smem with stride 65 (conflict-free). 256 threads, micro-tile 4 nodes x CPT.
#define A_STRIDE 65

template <int OUTC, bool RELU>
__global__ __launch_bounds__(256, 1)
void gemm_kernel(const float* __restrict__ agg, const float* __restrict__ xin,
                 const float* __restrict__ Wl, const float* __restrict__ Wr,
                 const float* __restrict__ bias, float* __restrict__ out, int N) {
    constexpr int CPT = OUTC / 16;  // cols per thread (8 or 4)
    extern __shared__ float smem[];
    float* Ws = smem;                  // [256][OUTC]
    float* As = smem + 256 * OUTC;     // [256][A_STRIDE], node-major rows

    int tid  = threadIdx.x;
    int lane = tid & 31;
    int wid  = tid >> 5;
    int cg   = tid & 15;   // col group
    int ng   = tid >> 4;   // node group (0..15), 4 nodes each

    // load weights: Ws[k][c] = Wl[k][c] (k<128), Wr[k-128][c] (k>=128)
    for (int idx = tid; idx < 128 * OUTC; idx += 256) {
        Ws[idx]              = Wl[idx];
        Ws[128 * OUTC + idx] = Wr[idx];
    }

    int nb = blockIdx.x * 64;

    // load A tile transposed: As[k][i] for i in [0,64)
    for (int i = wid; i < 64; i += 8) {
        int node = min(nb + i, N - 1);
        float4 va = ((const float4*)(agg + (size_t)node * HID))[lane];
        float4 vx = ((const float4*)(xin + (size_t)node * HID))[lane];
        int k0 = 4 * lane;
        As[(k0 + 0) * A_STRIDE + i] = va.x;
        As[(k0 + 1) * A_STRIDE + i] = va.y;
        As[(k0 + 2) * A_STRIDE + i] = va.z;
        As[(k0 + 3) * A_STRIDE + i] = va.w;
        As[(128 + k0 + 0) * A_STRIDE + i] = vx.x;
        As[(128 + k0 + 1) * A_STRIDE + i] = vx.y;
        As[(128 + k0 + 2) * A_STRIDE + i] = vx.z;
        As[(128 + k0 + 3) * A_STRIDE + i] = vx.w;
    }
    __syncthreads();

    float acc[4][CPT];
    #pragma unroll
    for (int r = 0; r < 4; r++)
        #pragma unroll
        for (int j = 0; j < CPT; j++) acc[r][j] = 0.f;

    int n0 = 4 * ng;
    int c0 = cg * CPT;

    #pragma unroll 8
    for (int k = 0; k < 256; k++) {
        float a0 = As[k * A_STRIDE + n0 + 0];
        float a1 = As[k * A_STRIDE + n0 + 1];
        float a2 = As[k * A_STRIDE + n0 + 2];
        float a3 = As[k * A_STRIDE + n0 + 3];
        float w[CPT];
        #pragma unroll
        for (int q = 0; q < CPT / 4; q++) {
            float4 wv = *(const float4*)&Ws[k * OUTC + c0 + 4 * q];
            w[4 * q + 0] = wv.x; w[4 * q + 1] = wv.y;
            w[4 * q + 2] = wv.z; w[4 * q + 3] = wv.w;
        }
        #pragma unroll
        for (int j = 0; j < CPT; j++) {
            acc[0][j] = fmaf(a0, w[j], acc[0][j]);
            acc[1][j] = fmaf(a1, w[j], acc[1][j]);
            acc[2][j] = fmaf(a2, w[j], acc[2][j]);
            acc[3][j] = fmaf(a3, w[j], acc[3][j]);
        }
    }

    #pragma unroll
    for (int r = 0; r < 4; r++) {
        int node = nb + n0 + r;
        if (node < N) {
            #pragma unroll
            for (int j = 0; j < CPT; j++) {
                float v = acc[r][j] + bias[c0 + j];
                if (RELU) v = fmaxf(v, 0.f);
                out[(size_t)node * OUTC + c0 + j] = v;
            }
        }
    }
}

// ---------------- launch ------------------------------------------------------
extern "C" void kernel_launch(void* const* d_in, const int* in_sizes, int n_in,
                              void* d_out, int out_size) {
    const float* x   = (const float*)d_in[0];
    const int*   ei  = (const int*)  d_in[1];
    const float* W1l = (const float*)d_in[2];
    const float* W1r = (const float*)d_in[3];
    const float* b1  = (const float*)d_in[4];
    const float* W2l = (const float*)d_in[5];
    const float* W2r = (const float*)d_in[6];
    const float* b2  = (const float*)d_in[7];
    const float* W3l = (const float*)d_in[8];
    const float* W3r = (const float*)d_in[9];
    const float* b3  = (const float*)d_in[10];
    float* out = (float*)d_out;

    int N = in_sizes[0] / HID;
    int E = in_sizes[1] / 2;
    const int* src = ei;
    const int* dst = ei + E;

    int*   deg;  cudaGetSymbolAddress((void**)&deg,  g_deg);
    int*   off;  cudaGetSymbolAddress((void**)&off,  g_off);
    int*   cur;  cudaGetSymbolAddress((void**)&cur,  g_cursor);
    int*   srcs; cudaGetSymbolAddress((void**)&srcs, g_srcs);
    float* agg;  cudaGetSymbolAddress((void**)&agg,  g_agg);
    float* h1;   cudaGetSymbolAddress((void**)&h1,   g_h1);
    float* h2;   cudaGetSymbolAddress((void**)&h2,   g_h2);

    // CSR build (once per launch — same edges for all 3 layers)
    zero_deg_kernel<<<(N + 255) / 256, 256>>>(deg, N);
    count_deg_kernel<<<(E + 255) / 256, 256>>>(dst, deg, E);
    scan_kernel<<<1, 1024>>>(deg, off, N);
    copy_cursor_kernel<<<(N + 255) / 256, 256>>>(off, cur, N);
    fill_csr_kernel<<<(E + 255) / 256, 256>>>(src, dst, cur, srcs, E);

    int aggBlocks  = (N * 32 + 255) / 256;
    int gemmBlocks = (N + 63) / 64;

    size_t smem128 = (size_t)(256 * 128 + 256 * A_STRIDE) * sizeof(float);
    size_t smem64  = (size_t)(256 * 64  + 256 * A_STRIDE) * sizeof(float);
    cudaFuncSetAttribute(gemm_kernel<128, true>,
                         cudaFuncAttributeMaxDynamicSharedMemorySize, (int)smem128);
    cudaFuncSetAttribute(gemm_kernel<64, false>,
                         cudaFuncAttributeMaxDynamicSharedMemorySize, (int)smem64);

    // layer 1
    agg_kernel<<<aggBlocks, 256>>>(x, agg, off, srcs, N);
    gemm_kernel<128, true><<<gemmBlocks, 256, smem128>>>(agg, x, W1l, W1r, b1, h1, N);
    // layer 2
    agg_kernel<<<aggBlocks, 256>>>(h1, agg, off, srcs, N);
    gemm_kernel<128, true><<<gemmBlocks, 256, smem128>>>(agg, h1, W2l, W2r, b2, h2, N);
    // layer 3
    agg_kernel<<<aggBlocks, 256>>>(h2, agg, off, srcs, N);
    gemm_kernel<64, false><<<gemmBlocks, 256, smem64>>>(agg, h2, W3l, W3r, b3, out, N);
}

// round 2
// speedup vs baseline: 2.2786x; 2.2786x over previous
#include <cuda_runtime.h>
#include <cuda_bf16.h>
#include <cstdint>

#define N_NODES 50000
#define N_EDGES 500000
#define HID 128

// ---------------- scratch (device globals; no allocations allowed) ------------
__device__ int   g_deg[N_NODES];
__device__ int   g_off[N_NODES + 1];
__device__ int   g_cursor[N_NODES];
__device__ int   g_srcs[N_EDGES];
__device__ float g_agg[(size_t)N_NODES * HID];
__device__ float g_h1 [(size_t)N_NODES * HID];
__device__ float g_h2 [(size_t)N_NODES * HID];

// ---------------- CSR build ---------------------------------------------------
__global__ void zero_deg_kernel(int* deg, int n) {
    int i = blockIdx.x * blockDim.x + threadIdx.x;
    if (i < n) deg[i] = 0;
}

__global__ void count_deg_kernel(const int* __restrict__ dst, int* __restrict__ deg, int E) {
    int e = blockIdx.x * blockDim.x + threadIdx.x;
    if (e < E) atomicAdd(&deg[dst[e]], 1);
}

// single-block scan, 1024 threads; writes off[] and cur[] (cursor copy fused in)
__global__ void scan_kernel(const int* __restrict__ deg, int* __restrict__ off,
                            int* __restrict__ cur, int N) {
    __shared__ int warp_sums[32];
    __shared__ int s_carry;
    int tid = threadIdx.x, lane = tid & 31, wid = tid >> 5;
    if (tid == 0) s_carry = 0;
    __syncthreads();
    for (int base = 0; base < N; base += 4096) {
        int idx = base + tid * 4;
        int v0 = (idx + 0 < N) ? deg[idx + 0] : 0;
        int v1 = (idx + 1 < N) ? deg[idx + 1] : 0;
        int v2 = (idx + 2 < N) ? deg[idx + 2] : 0;
        int v3 = (idx + 3 < N) ? deg[idx + 3] : 0;
        int s1 = v0, s2 = s1 + v1, s3 = s2 + v2, s4 = s3 + v3;
        int x = s4;
        #pragma unroll
        for (int o = 1; o < 32; o <<= 1) {
            int t = __shfl_up_sync(0xFFFFFFFFu, x, o);
            if (lane >= o) x += t;
        }
        if (lane == 31) warp_sums[wid] = x;
        __syncthreads();
        if (wid == 0) {
            int y = warp_sums[lane];
            #pragma unroll
            for (int o = 1; o < 32; o <<= 1) {
                int t = __shfl_up_sync(0xFFFFFFFFu, y, o);
                if (lane >= o) y += t;
            }
            warp_sums[lane] = y;
        }
        __syncthreads();
        int warp_off = (wid > 0) ? warp_sums[wid - 1] : 0;
        int excl = (x - s4) + warp_off + s_carry;
        if (idx + 0 < N) { off[idx + 0] = excl;      cur[idx + 0] = excl;      }
        if (idx + 1 < N) { off[idx + 1] = excl + s1; cur[idx + 1] = excl + s1; }
        if (idx + 2 < N) { off[idx + 2] = excl + s2; cur[idx + 2] = excl + s2; }
        if (idx + 3 < N) { off[idx + 3] = excl + s3; cur[idx + 3] = excl + s3; }
        __syncthreads();
        if (tid == 0) s_carry += warp_sums[31];
        __syncthreads();
    }
    if (threadIdx.x == 0) off[N] = s_carry;
}

__global__ void fill_csr_kernel(const int* __restrict__ src, const int* __restrict__ dst,
                                int* __restrict__ cur, int* __restrict__ srcs, int E) {
    int e = blockIdx.x * blockDim.x + threadIdx.x;
    if (e < E) {
        int d = dst[e];
        int pos = atomicAdd(&cur[d], 1);
        srcs[pos] = src[e];
    }
}

// ---------------- mean aggregation: one warp per node -------------------------
__global__ void agg_kernel(const float* __restrict__ x, float* __restrict__ agg,
                           const int* __restrict__ off, const int* __restrict__ srcs, int N) {
    int warp = (blockIdx.x * blockDim.x + threadIdx.x) >> 5;
    int lane = threadIdx.x & 31;
    if (warp >= N) return;
    int s = off[warp], e = off[warp + 1];
    float4 acc = make_float4(0.f, 0.f, 0.f, 0.f);
    for (int j = s; j < e; ++j) {
        int u = srcs[j];
        float4 v = ((const float4*)(x + (size_t)u * HID))[lane];
        acc.x += v.x; acc.y += v.y; acc.z += v.z; acc.w += v.w;
    }
    float inv = 1.0f / (float)max(e - s, 1);
    acc.x *= inv; acc.y *= inv; acc.z *= inv; acc.w *= inv;
    ((float4*)(agg + (size_t)warp * HID))[lane] = acc;
}

// ---------------- TF32 tensor-core GEMM --------------------------------------
// out[n, :] = relu?( agg[n,:] @ Wl + x[n,:] @ Wr + b ), K=256 total.
// CTA tile: 128 nodes x OUTC. 8 warps; warp tile 32 nodes x OUTC/2.
// K processed in 4 chunks of 64 (agg/Wl halves then x/Wr halves).

__device__ __forceinline__ uint32_t f2tf32(float f) {
    uint32_t r;
    asm("cvt.rna.tf32.f32 %0, %1;" : "=r"(r) : "f"(f));
    return r;
}

__device__ __forceinline__ void mma_tf32(float* d, const uint32_t* a, const uint32_t* b) {
    asm volatile(
        "mma.sync.aligned.m16n8k8.row.col.f32.tf32.tf32.f32 "
        "{%0,%1,%2,%3}, {%4,%5,%6,%7}, {%8,%9}, {%0,%1,%2,%3};"
        : "+f"(d[0]), "+f"(d[1]), "+f"(d[2]), "+f"(d[3])
        : "r"(a[0]), "r"(a[1]), "r"(a[2]), "r"(a[3]), "r"(b[0]), "r"(b[1]));
}

template <int OUTC, bool RELU>
__global__ __launch_bounds__(256, 2)
void gemm_tc(const float* __restrict__ agg, const float* __restrict__ xin,
             const float* __restrict__ Wl, const float* __restrict__ Wr,
             const float* __restrict__ bias, float* __restrict__ out, int N) {
    constexpr int NT = OUTC / 16;                 // 8x8 n-tiles per warp
    constexpr int AS = 68;                        // A smem stride (mod 32 == 4: conflict-free)
    constexpr int WS = (OUTC == 128) ? 136 : 72;  // W smem stride (mod 32 == 8: conflict-free)

    extern __shared__ uint32_t sm[];
    uint32_t* As = sm;                 // [128][AS]  tf32 bits
    uint32_t* Ws = sm + 128 * AS;      // [64][WS]   tf32 bits

    int tid  = threadIdx.x;
    int lane = tid & 31;
    int wid  = tid >> 5;
    int nb   = blockIdx.x * 128;
    int wn   = 32 * (wid >> 1);        // warp node base (local)
    int wc   = (OUTC / 2) * (wid & 1); // warp col base
    int g    = lane >> 2;              // group id 0..7
    int t    = lane & 3;               // thread-in-group 0..3

    float acc[2][NT][4];
    #pragma unroll
    for (int mr = 0; mr < 2; mr++)
        #pragma unroll
        for (int nt = 0; nt < NT; nt++)
            #pragma unroll
            for (int q = 0; q < 4; q++) acc[mr][nt][q] = 0.f;

    #pragma unroll
    for (int chunk = 0; chunk < 4; chunk++) {
        const float* Asrc = (chunk < 2) ? agg : xin;
        const float* Wsrc = (chunk < 2) ? Wl : Wr;
        int kb = (chunk & 1) * 64;

        __syncthreads();   // previous chunk's compute done before overwrite

        // load A chunk: 128 nodes x 64 k = 2048 float4
        #pragma unroll
        for (int it = 0; it < 8; it++) {
            int idx  = it * 256 + tid;
            int node = idx >> 4;
            int k4   = idx & 15;
            int gn   = min(nb + node, N - 1);
            float4 v = ((const float4*)(Asrc + (size_t)gn * HID + kb))[k4];
            uint4 u  = make_uint4(f2tf32(v.x), f2tf32(v.y), f2tf32(v.z), f2tf32(v.w));
            *(uint4*)(As + node * AS + 4 * k4) = u;
        }
        // load W chunk: 64 rows x OUTC
        constexpr int WIT = (64 * OUTC / 4) / 256;
        #pragma unroll
        for (int it = 0; it < WIT; it++) {
            int idx = it * 256 + tid;
            int r   = idx / (OUTC / 4);
            int c4  = idx % (OUTC / 4);
            float4 v = ((const float4*)(Wsrc + (size_t)(kb + r) * OUTC))[c4];
            uint4 u  = make_uint4(f2tf32(v.x), f2tf32(v.y), f2tf32(v.z), f2tf32(v.w));
            *(uint4*)(Ws + r * WS + 4 * c4) = u;
        }
        __syncthreads();

        // compute: 8 k-steps of 8
        #pragma unroll
        for (int kk = 0; kk < 64; kk += 8) {
            uint32_t a[2][4];
            #pragma unroll
            for (int mr = 0; mr < 2; mr++) {
                int r0 = wn + 16 * mr + g;
                a[mr][0] = As[r0 * AS + kk + t];
                a[mr][1] = As[(r0 + 8) * AS + kk + t];
                a[mr][2] = As[r0 * AS + kk + t + 4];
                a[mr][3] = As[(r0 + 8) * AS + kk + t + 4];
            }
            uint32_t b[NT][2];
            #pragma unroll
            for (int nt = 0; nt < NT; nt++) {
                int c = wc + 8 * nt + g;
                b[nt][0] = Ws[(kk + t) * WS + c];
                b[nt][1] = Ws[(kk + t + 4) * WS + c];
            }
            #pragma unroll
            for (int mr = 0; mr < 2; mr++)
                #pragma unroll
                for (int nt = 0; nt < NT; nt++)
                    mma_tf32(acc[mr][nt], a[mr], b[nt]);
        }
    }

    // epilogue: bias (+relu), float2 stores
    #pragma unroll
    for (int mr = 0; mr < 2; mr++) {
        #pragma unroll
        for (int nt = 0; nt < NT; nt++) {
            int col = wc + 8 * nt + 2 * t;
            float bx = bias[col], by = bias[col + 1];
            int row0 = nb + wn + 16 * mr + g;
            if (row0 < N) {
                float v0 = acc[mr][nt][0] + bx;
                float v1 = acc[mr][nt][1] + by;
                if (RELU) { v0 = fmaxf(v0, 0.f); v1 = fmaxf(v1, 0.f); }
                *(float2*)(out + (size_t)row0 * OUTC + col) = make_float2(v0, v1);
            }
            int row1 = row0 + 8;
            if (row1 < N) {
                float v0 = acc[mr][nt][2] + bx;
                float v1 = acc[mr][nt][3] + by;
                if (RELU) { v0 = fmaxf(v0, 0.f); v1 = fmaxf(v1, 0.f); }
                *(float2*)(out + (size_t)row1 * OUTC + col) = make_float2(v0, v1);
            }
        }
    }
}

// ---------------- launch ------------------------------------------------------
extern "C" void kernel_launch(void* const* d_in, const int* in_sizes, int n_in,
                              void* d_out, int out_size) {
    const float* x   = (const float*)d_in[0];
    const int*   ei  = (const int*)  d_in[1];
    const float* W1l = (const float*)d_in[2];
    const float* W1r = (const float*)d_in[3];
    const float* b1  = (const float*)d_in[4];
    const float* W2l = (const float*)d_in[5];
    const float* W2r = (const float*)d_in[6];
    const float* b2  = (const float*)d_in[7];
    const float* W3l = (const float*)d_in[8];
    const float* W3r = (const float*)d_in[9];
    const float* b3  = (const float*)d_in[10];
    float* out = (float*)d_out;

    int N = in_sizes[0] / HID;
    int E = in_sizes[1] / 2;
    const int* src = ei;
    const int* dst = ei + E;

    int*   deg;  cudaGetSymbolAddress((void**)&deg,  g_deg);
    int*   off;  cudaGetSymbolAddress((void**)&off,  g_off);
    int*   cur;  cudaGetSymbolAddress((void**)&cur,  g_cursor);
    int*   srcs; cudaGetSymbolAddress((void**)&srcs, g_srcs);
    float* agg;  cudaGetSymbolAddress((void**)&agg,  g_agg);
    float* h1;   cudaGetSymbolAddress((void**)&h1,   g_h1);
    float* h2;   cudaGetSymbolAddress((void**)&h2,   g_h2);

    // CSR build (once per launch)
    zero_deg_kernel<<<(N + 255) / 256, 256>>>(deg, N);
    count_deg_kernel<<<(E + 255) / 256, 256>>>(dst, deg, E);
    scan_kernel<<<1, 1024>>>(deg, off, cur, N);
    fill_csr_kernel<<<(E + 255) / 256, 256>>>(src, dst, cur, srcs, E);

    int aggBlocks  = (N * 32 + 255) / 256;
    int gemmBlocks = (N + 127) / 128;

    size_t smem128 = (size_t)(128 * 68 + 64 * 136) * sizeof(uint32_t);  // 69632 B
    size_t smem64  = (size_t)(128 * 68 + 64 * 72)  * sizeof(uint32_t);  // 53248 B
    cudaFuncSetAttribute(gemm_tc<128, true>,
                         cudaFuncAttributeMaxDynamicSharedMemorySize, (int)smem128);
    cudaFuncSetAttribute(gemm_tc<64, false>,
                         cudaFuncAttributeMaxDynamicSharedMemorySize, (int)smem64);

    // layer 1
    agg_kernel<<<aggBlocks, 256>>>(x, agg, off, srcs, N);
    gemm_tc<128, true><<<gemmBlocks, 256, smem128>>>(agg, x, W1l, W1r, b1, h1, N);
    // layer 2
    agg_kernel<<<aggBlocks, 256>>>(h1, agg, off, srcs, N);
    gemm_tc<128, true><<<gemmBlocks, 256, smem128>>>(agg, h1, W2l, W2r, b2, h2, N);
    // layer 3
    agg_kernel<<<aggBlocks, 256>>>(h2, agg, off, srcs, N);
    gemm_tc<64, false><<<gemmBlocks, 256, smem64>>>(agg, h2, W3l, W3r, b3, out, N);
}

// round 4
// speedup vs baseline: 3.9496x; 1.7333x over previous
#include <cuda_runtime.h>
#include <cuda_fp16.h>
#include <cstdint>

#define N_NODES 50000
#define N_EDGES 500000
#define HID 128

// ---------------- scratch (device globals) ------------------------------------
__device__ int    g_deg[N_NODES];
__device__ int    g_off[N_NODES + 1];
__device__ int    g_cursor[N_NODES];
__device__ int    g_bsum[256];
__device__ int    g_srcs[N_EDGES];
__device__ __half g_xh [(size_t)N_NODES * HID];
__device__ __half g_agg[(size_t)N_NODES * HID];
__device__ __half g_h1 [(size_t)N_NODES * HID];
__device__ __half g_h2 [(size_t)N_NODES * HID];

// ---------------- small helpers -----------------------------------------------
__device__ __forceinline__ uint32_t smem_u32(const void* p) {
    uint32_t a;
    asm("{ .reg .u64 t; cvta.to.shared.u64 t, %1; cvt.u32.u64 %0, t; }" : "=r"(a) : "l"(p));
    return a;
}

#define LDSM_X4(r, a) \
    asm volatile("ldmatrix.sync.aligned.m8n8.x4.shared.b16 {%0,%1,%2,%3}, [%4];" \
                 : "=r"((r)[0]), "=r"((r)[1]), "=r"((r)[2]), "=r"((r)[3]) : "r"(a))
#define LDSM_X4T(r0, r1, r2, r3, a) \
    asm volatile("ldmatrix.sync.aligned.m8n8.x4.trans.shared.b16 {%0,%1,%2,%3}, [%4];" \
                 : "=r"(r0), "=r"(r1), "=r"(r2), "=r"(r3) : "r"(a))

__device__ __forceinline__ void mma_f16(float* d, const uint32_t* a, const uint32_t* b) {
    asm volatile(
        "mma.sync.aligned.m16n8k16.row.col.f32.f16.f16.f32 "
        "{%0,%1,%2,%3}, {%4,%5,%6,%7}, {%8,%9}, {%0,%1,%2,%3};"
        : "+f"(d[0]), "+f"(d[1]), "+f"(d[2]), "+f"(d[3])
        : "r"(a[0]), "r"(a[1]), "r"(a[2]), "r"(a[3]), "r"(b[0]), "r"(b[1]));
}

// ---------------- CSR build ---------------------------------------------------
__global__ void zero_deg_kernel(int* deg, int n) {
    int i = blockIdx.x * blockDim.x + threadIdx.x;
    if (i < n) deg[i] = 0;
}
__global__ void count_deg_kernel(const int* __restrict__ dst, int* __restrict__ deg, int E) {
    int e = blockIdx.x * blockDim.x + threadIdx.x;
    if (e < E) atomicAdd(&deg[dst[e]], 1);
}

__device__ __forceinline__ int block_scan256(int v, int* ws) {
    int lane = threadIdx.x & 31, w = threadIdx.x >> 5;
    int x = v;
    #pragma unroll
    for (int o = 1; o < 32; o <<= 1) {
        int t = __shfl_up_sync(0xFFFFFFFFu, x, o);
        if (lane >= o) x += t;
    }
    if (lane == 31) ws[w] = x;
    __syncthreads();
    if (w == 0) {
        int y = (lane < 8) ? ws[lane] : 0;
        #pragma unroll
        for (int o = 1; o < 8; o <<= 1) {
            int t = __shfl_up_sync(0xFFFFFFFFu, y, o);
            if (lane >= o) y += t;
        }
        if (lane < 8) ws[lane] = y;
    }
    __syncthreads();
    int base = (w > 0) ? ws[w - 1] : 0;
    return x + base;
}

__global__ void scan_partial(const int* __restrict__ deg, int* __restrict__ off,
                             int* __restrict__ bsum, int N) {
    __shared__ int ws[8];
    int i = blockIdx.x * 256 + threadIdx.x;
    int v = (i < N) ? deg[i] : 0;
    int incl = block_scan256(v, ws);
    if (i < N) off[i] = incl - v;
    if (threadIdx.x == 255) bsum[blockIdx.x] = incl;
}
__global__ void scan_sums(int* __restrict__ bsum, int* __restrict__ offN, int nblk) {
    __shared__ int ws[8];
    int t = threadIdx.x;
    int v = (t < nblk) ? bsum[t] : 0;
    int incl = block_scan256(v, ws);
    if (t < nblk) bsum[t] = incl - v;
    if (t == 255) *offN = incl;
}
__global__ void add_off(int* __restrict__ off, int* __restrict__ cur,
                        const int* __restrict__ bsum, int N) {
    int i = blockIdx.x * 256 + threadIdx.x;
    if (i < N) {
        int v = off[i] + bsum[blockIdx.x];
        off[i] = v;
        cur[i] = v;
    }
}
__global__ void fill_csr_kernel(const int* __restrict__ src, const int* __restrict__ dst,
                                int* __restrict__ cur, int* __restrict__ srcs, int E) {
    int e = blockIdx.x * blockDim.x + threadIdx.x;
    if (e < E) {
        int pos = atomicAdd(&cur[dst[e]], 1);
        srcs[pos] = src[e];
    }
}

// ---------------- x -> fp16 conversion ----------------------------------------
__global__ void conv_f16_kernel(const float* __restrict__ x, __half* __restrict__ xh,
                                int total8) {
    int i = blockIdx.x * blockDim.x + threadIdx.x;
    if (i >= total8) return;
    const float4* p = (const float4*)(x + (size_t)i * 8);
    float4 a = p[0], b = p[1];
    __half2 h0 = __float22half2_rn(make_float2(a.x, a.y));
    __half2 h1 = __float22half2_rn(make_float2(a.z, a.w));
    __half2 h2 = __float22half2_rn(make_float2(b.x, b.y));
    __half2 h3 = __float22half2_rn(make_float2(b.z, b.w));
    uint4 u;
    u.x = *(uint32_t*)&h0; u.y = *(uint32_t*)&h1;
    u.z = *(uint32_t*)&h2; u.w = *(uint32_t*)&h3;
    *(uint4*)(xh + (size_t)i * 8) = u;
}

// ---------------- mean aggregation (fp16 features, fp32 accum) ----------------
__global__ void agg_f16_kernel(const __half* __restrict__ x, __half* __restrict__ agg,
                               const int* __restrict__ off, const int* __restrict__ srcs,
                               int N) {
    int warp = (blockIdx.x * blockDim.x + threadIdx.x) >> 5;
    int lane = threadIdx.x & 31;
    if (warp >= N) return;
    int s = off[warp], e = off[warp + 1];
    float4 acc = make_float4(0.f, 0.f, 0.f, 0.f);
    int j = s;
    for (; j + 1 < e; j += 2) {
        int u0 = srcs[j], u1 = srcs[j + 1];
        uint2 p0 = *(const uint2*)(x + (size_t)u0 * HID + 4 * lane);
        uint2 p1 = *(const uint2*)(x + (size_t)u1 * HID + 4 * lane);
        float2 a0 = __half22float2(*(__half2*)&p0.x);
        float2 a1 = __half22float2(*(__half2*)&p0.y);
        float2 b0 = __half22float2(*(__half2*)&p1.x);
        float2 b1 = __half22float2(*(__half2*)&p1.y);
        acc.x += a0.x + b0.x; acc.y += a0.y + b0.y;
        acc.z += a1.x + b1.x; acc.w += a1.y + b1.y;
    }
    if (j < e) {
        int u0 = srcs[j];
        uint2 p0 = *(const uint2*)(x + (size_t)u0 * HID + 4 * lane);
        float2 a0 = __half22float2(*(__half2*)&p0.x);
        float2 a1 = __half22float2(*(__half2*)&p0.y);
        acc.x += a0.x; acc.y += a0.y; acc.z += a1.x; acc.w += a1.y;
    }
    float inv = 1.0f / (float)max(e - s, 1);
    __half2 o0 = __float22half2_rn(make_float2(acc.x * inv, acc.y * inv));
    __half2 o1 = __float22half2_rn(make_float2(acc.z * inv, acc.w * inv));
    uint2 o;
    o.x = *(uint32_t*)&o0; o.y = *(uint32_t*)&o1;
    *(uint2*)(agg + (size_t)warp * HID + 4 * lane) = o;
}

// ---------------- fp16 tensor-core GEMM ----------------------------------------
// out[n,:] = relu?( agg[n,:]@Wl + xin[n,:]@Wr + b ).  CTA: 128 nodes x OUTC.
// K=256 as 4 chunks of 64.  ldmatrix fragment loads; custom XOR swizzle.
// A smem: [128 nodes][64 k] fp16, addr = row*128 + ((2k) ^ ((row&7)*16))
// B smem: [64 k][OUTC n] fp16 (as in gmem), addr = k*(2*OUTC) + ((2n) ^ ((k&7)*16))

template <int OUTC, bool RELU, typename OT>
__global__ __launch_bounds__(256, 2)
void gemm_f16(const __half* __restrict__ agg, const __half* __restrict__ xin,
              const float* __restrict__ Wl, const float* __restrict__ Wr,
              const float* __restrict__ bias, OT* __restrict__ out, int N) {
    constexpr int NT = OUTC / 16;          // n-tiles (8 wide) per warp
    extern __shared__ char smem[];
    uint32_t sA = smem_u32(smem);          // 16 KB
    uint32_t sB = sA + 16384;              // OUTC*128 bytes

    int tid = threadIdx.x, lane = tid & 31, wid = tid >> 5;
    int nb = blockIdx.x * 128;
    int wn = 32 * (wid >> 1);
    int wc = (OUTC / 2) * (wid & 1);
    int g  = lane >> 2;
    int t  = lane & 3;

    float acc[2][NT][4];
    #pragma unroll
    for (int mt = 0; mt < 2; mt++)
        #pragma unroll
        for (int nt = 0; nt < NT; nt++)
            #pragma unroll
            for (int q = 0; q < 4; q++) acc[mt][nt][q] = 0.f;

    // precomputed ldmatrix lane addressing pieces
    int lrow = lane & 7;
    int selA_r = ((lane >> 3) & 1) * 8;    // +8 rows for mats 1,3
    int selA_k = ((lane >> 4) & 1) * 8;    // +8 k for mats 2,3
    int selB_k = ((lane >> 3) & 1) * 8;
    int selB_n = ((lane >> 4) & 1) * 8;

    #pragma unroll
    for (int chunk = 0; chunk < 4; chunk++) {
        const __half* Asrc = (chunk < 2) ? agg : xin;
        const float*  Wsrc = (chunk < 2) ? Wl : Wr;
        int kb = (chunk & 1) * 64;

        __syncthreads();  // previous compute done before overwrite

        // fill A: 128 nodes x 64 k halves = 1024 x 16B
        #pragma unroll
        for (int it = 0; it < 4; it++) {
            int idx = it * 256 + tid;
            int node = idx >> 3, u8 = idx & 7;
            int gn = min(nb + node, N - 1);
            uint4 v = *(const uint4*)(Asrc + (size_t)gn * HID + kb + 8 * u8);
            uint32_t off = node * 128 + ((u8 * 16) ^ ((node & 7) * 16));
            *(uint4*)(smem + off) = v;
        }
        // fill B: 64 k rows x OUTC halves (convert fp32 -> fp16), 8 halves/task
        constexpr int BTASK = 64 * (OUTC / 8);
        #pragma unroll
        for (int it = 0; it < BTASK / 256; it++) {
            int idx = it * 256 + tid;
            int k = idx / (OUTC / 8), u = idx % (OUTC / 8);
            const float4* wp = (const float4*)(Wsrc + (size_t)(kb + k) * OUTC + 8 * u);
            float4 a = wp[0], b = wp[1];
            __half2 h0 = __float22half2_rn(make_float2(a.x, a.y));
            __half2 h1 = __float22half2_rn(make_float2(a.z, a.w));
            __half2 h2 = __float22half2_rn(make_float2(b.x, b.y));
            __half2 h3 = __float22half2_rn(make_float2(b.z, b.w));
            uint4 v;
            v.x = *(uint32_t*)&h0; v.y = *(uint32_t*)&h1;
            v.z = *(uint32_t*)&h2; v.w = *(uint32_t*)&h3;
            uint32_t off = k * (2 * OUTC) + ((u * 16) ^ ((k & 7) * 16));
            *(uint4*)(smem + 16384 + off) = v;
        }
        __syncthreads();

        // compute: 4 k-steps of 16
        #pragma unroll
        for (int ks = 0; ks < 4; ks++) {
            int k0 = 16 * ks;
            uint32_t a[2][4];
            #pragma unroll
            for (int mt = 0; mt < 2; mt++) {
                int row = wn + 16 * mt + selA_r + lrow;
                int kc  = k0 + selA_k;
                uint32_t addr = sA + row * 128 + ((2 * kc) ^ ((row & 7) * 16));
                LDSM_X4(a[mt], addr);
            }
            uint32_t b[NT][2];
            #pragma unroll
            for (int p = 0; p < NT / 2; p++) {
                int krow = k0 + selB_k + lrow;
                int ncol = wc + 16 * p + selB_n;
                uint32_t addr = sB + krow * (2 * OUTC) + ((2 * ncol) ^ ((krow & 7) * 16));
                LDSM_X4T(b[2 * p][0], b[2 * p][1], b[2 * p + 1][0], b[2 * p + 1][1], addr);
            }
            #pragma unroll
            for (int mt = 0; mt < 2; mt++)
                #pragma unroll
                for (int nt = 0; nt < NT; nt++)
                    mma_f16(acc[mt][nt], a[mt], b[nt]);
        }
    }

    // epilogue
    #pragma unroll
    for (int mt = 0; mt < 2; mt++) {
        #pragma unroll
        for (int nt = 0; nt < NT; nt++) {
            int col = wc + 8 * nt + 2 * t;
            float bx = bias[col], by = bias[col + 1];
            int row0 = nb + wn + 16 * mt + g;
            int row1 = row0 + 8;
            float v0 = acc[mt][nt][0] + bx, v1 = acc[mt][nt][1] + by;
            float v2 = acc[mt][nt][2] + bx, v3 = acc[mt][nt][3] + by;
            if (RELU) {
                v0 = fmaxf(v0, 0.f); v1 = fmaxf(v1, 0.f);
                v2 = fmaxf(v2, 0.f); v3 = fmaxf(v3, 0.f);
            }
            if (row0 < N) {
                if constexpr (sizeof(OT) == 2) {
                    __half2 h = __float22half2_rn(make_float2(v0, v1));
                    *(uint32_t*)((__half*)out + (size_t)row0 * OUTC + col) = *(uint32_t*)&h;
                } else {
                    *(float2*)((float*)out + (size_t)row0 * OUTC + col) = make_float2(v0, v1);
                }
            }
            if (row1 < N) {
                if constexpr (sizeof(OT) == 2) {
                    __half2 h = __float22half2_rn(make_float2(v2, v3));
                    *(uint32_t*)((__half*)out + (size_t)row1 * OUTC + col) = *(uint32_t*)&h;
                } else {
                    *(float2*)((float*)out + (size_t)row1 * OUTC + col) = make_float2(v2, v3);
                }
            }
        }
    }
}

// ---------------- launch ------------------------------------------------------
extern "C" void kernel_launch(void* const* d_in, const int* in_sizes, int n_in,
                              void* d_out, int out_size) {
    const float* x   = (const float*)d_in[0];
    const int*   ei  = (const int*)  d_in[1];
    const float* W1l = (const float*)d_in[2];
    const float* W1r = (const float*)d_in[3];
    const float* b1  = (const float*)d_in[4];
    const float* W2l = (const float*)d_in[5];
    const float* W2r = (const float*)d_in[6];
    const float* b2  = (const float*)d_in[7];
    const float* W3l = (const float*)d_in[8];
    const float* W3r = (const float*)d_in[9];
    const float* b3  = (const float*)d_in[10];
    float* out = (float*)d_out;

    int N = in_sizes[0] / HID;
    int E = in_sizes[1] / 2;
    const int* src = ei;
    const int* dst = ei + E;

    int*    deg;  cudaGetSymbolAddress((void**)&deg,  g_deg);
    int*    off;  cudaGetSymbolAddress((void**)&off,  g_off);
    int*    cur;  cudaGetSymbolAddress((void**)&cur,  g_cursor);
    int*    bsum; cudaGetSymbolAddress((void**)&bsum, g_bsum);
    int*    srcs; cudaGetSymbolAddress((void**)&srcs, g_srcs);
    __half* xh;   cudaGetSymbolAddress((void**)&xh,   g_xh);
    __half* agg;  cudaGetSymbolAddress((void**)&agg,  g_agg);
    __half* h1;   cudaGetSymbolAddress((void**)&h1,   g_h1);
    __half* h2;   cudaGetSymbolAddress((void**)&h2,   g_h2);

    int nblk = (N + 255) / 256;

    // x -> fp16 (independent of CSR build)
    int total8 = N * HID / 8;
    conv_f16_kernel<<<(total8 + 255) / 256, 256>>>(x, xh, total8);

    // CSR build
    zero_deg_kernel<<<nblk, 256>>>(deg, N);
    count_deg_kernel<<<(E + 255) / 256, 256>>>(dst, deg, E);
    scan_partial<<<nblk, 256>>>(deg, off, bsum, N);
    scan_sums<<<1, 256>>>(bsum, off + N, nblk);
    add_off<<<nblk, 256>>>(off, cur, bsum, N);
    fill_csr_kernel<<<(E + 255) / 256, 256>>>(src, dst, cur, srcs, E);

    int aggBlocks  = (N * 32 + 255) / 256;
    int gemmBlocks = (N + 127) / 128;

    size_t smem128 = 16384 + (size_t)128 * 128;  // 32 KB
    size_t smem64  = 16384 + (size_t)64 * 128;   // 24 KB

    // layer 1
    agg_f16_kernel<<<aggBlocks, 256>>>(xh, agg, off, srcs, N);
    gemm_f16<128, true, __half><<<gemmBlocks, 256, smem128>>>(agg, xh, W1l, W1r, b1, h1, N);
    // layer 2
    agg_f16_kernel<<<aggBlocks, 256>>>(h1, agg, off, srcs, N);
    gemm_f16<128, true, __half><<<gemmBlocks, 256, smem128>>>(agg, h1, W2l, W2r, b2, h2, N);
    // layer 3
    agg_f16_kernel<<<aggBlocks, 256>>>(h2, agg, off, srcs, N);
    gemm_f16<64, false, float><<<gemmBlocks, 256, smem64>>>(agg, h2, W3l, W3r, b3, out, N);
}